// round 4
// baseline (speedup 1.0000x reference)
#include <cuda_runtime.h>
#include <cuda_fp16.h>
#include <math.h>

// Persistent device scratch (no allocation allowed in kernel_launch).
__device__ float  g_master_pos[3];
__device__ __half g_score_h[100032];   // fp16 score table (padded)

// ---- packed f32x2 helpers (sm_100+ PTX; doubles fp32 FMA throughput) ------
__device__ __forceinline__ unsigned long long ffma2(unsigned long long a,
                                                    unsigned long long b,
                                                    unsigned long long c) {
    unsigned long long d;
    asm("fma.rn.f32x2 %0, %1, %2, %3;" : "=l"(d) : "l"(a), "l"(b), "l"(c));
    return d;
}
__device__ __forceinline__ unsigned long long pack2(float x, float y) {
    unsigned long long r;
    asm("mov.b64 %0, {%1, %2};" : "=l"(r) : "f"(x), "f"(y));
    return r;
}
__device__ __forceinline__ void unpack2(unsigned long long p, float& x, float& y) {
    asm("mov.b64 {%0, %1}, %2;" : "=f"(x), "=f"(y) : "l"(p));
}

// ---------------------------------------------------------------------------
// Kernel 1: locate master node (x_t[i,0]==1.0). float4 coalesced scan of the
// whole 7*N float buffer; a hit counts only if it lies in column 0.
// ---------------------------------------------------------------------------
__global__ void find_master_kernel(const float4* __restrict__ x4, int n4, int total,
                                   const float* __restrict__ x_t) {
    int m = blockIdx.x * blockDim.x + threadIdx.x;
    if (m < n4) {
        float4 v = __ldg(&x4[m]);
        int base = 4 * m;
        float vv[4] = {v.x, v.y, v.z, v.w};
#pragma unroll
        for (int t = 0; t < 4; t++) {
            int idx = base + t;
            if (vv[t] == 1.0f && idx % 7 == 0) {
                g_master_pos[0] = x_t[idx + 1];
                g_master_pos[1] = x_t[idx + 2];
                g_master_pos[2] = x_t[idx + 3];
            }
        }
    }
    // scalar tail
    if (m == 0) {
        for (int idx = n4 * 4; idx < total; idx++) {
            if (x_t[idx] == 1.0f && idx % 7 == 0) {
                g_master_pos[0] = x_t[idx + 1];
                g_master_pos[1] = x_t[idx + 2];
                g_master_pos[2] = x_t[idx + 3];
            }
        }
    }
}

// ---------------------------------------------------------------------------
// Kernel 2: per-node features + MLP (3->32->32->1) + sigmoid -> fp16 table.
// Layer 2 uses packed f32x2 FMA: W2 staged TRANSPOSED in SMEM so that an
// ulonglong2 (LDS.128) read yields weight pairs for outputs (j, j+1) directly.
// ---------------------------------------------------------------------------
#define NS_THREADS 256
__global__ void node_score_kernel(const float* __restrict__ x_t,
                                  const float* __restrict__ x_t_dt,
                                  const float* __restrict__ W1,
                                  const float* __restrict__ b1,
                                  const float* __restrict__ W2,
                                  const float* __restrict__ b2,
                                  const float* __restrict__ W3,
                                  const float* __restrict__ b3,
                                  int n_nodes) {
    __shared__ float sW1[96];
    __shared__ float sb1[32];
    __shared__ __align__(16) float sW2t[1024];   // transposed: [k][j]
    __shared__ __align__(16) float sb2[32];
    __shared__ float sW3[32];
    __shared__ float sb3;
    __shared__ float smx, smy, smz;
    __shared__ __align__(16) float sx[NS_THREADS * 7];
    __shared__ __align__(16) float sxd[NS_THREADS * 7];

    int t = threadIdx.x;
    for (int k = t; k < 96; k += NS_THREADS) sW1[k] = W1[k];
    // transpose while staging: sW2t[k*32 + j] = W2[j*32 + k]
    for (int idx = t; idx < 1024; idx += NS_THREADS) {
        int j = idx >> 5, k = idx & 31;
        sW2t[k * 32 + j] = W2[idx];
    }
    if (t < 32) {
        sb1[t] = b1[t];
        sb2[t] = b2[t];
        sW3[t] = W3[t];
    }
    if (t == 0) {
        sb3 = b3[0];
        smx = g_master_pos[0];
        smy = g_master_pos[1];
        smz = g_master_pos[2];
    }

    // Coalesced staging of this block's node rows.
    int base_node = blockIdx.x * NS_THREADS;
    int nrows = min(NS_THREADS, n_nodes - base_node);
    int nflt = nrows * 7;
    const float* xr  = x_t    + (size_t)base_node * 7;
    const float* xdr = x_t_dt + (size_t)base_node * 7;
    for (int k = t; k < nflt; k += NS_THREADS) {
        sx[k]  = xr[k];
        sxd[k] = xdr[k];
    }
    __syncthreads();

    if (t >= nrows) return;
    int i = base_node + t;

    float px = sx[t * 7 + 1];
    float py = sx[t * 7 + 2];
    float pz = sx[t * 7 + 3];
    float dx = sxd[t * 7 + 1] - px;
    float dy = sxd[t * 7 + 2] - py;
    float dz = sxd[t * 7 + 3] - pz;

    float dn = sqrtf(dx * dx + dy * dy + dz * dz);   // velocity_score
    float inv_dn = 1.0f / fmaxf(dn, 1e-12f);         // dt = 1
    float vx = dx * inv_dn, vy = dy * inv_dn, vz = dz * inv_dn;

    float rx = px - smx, ry = py - smy, rz = pz - smz;
    float rn = sqrtf(rx * rx + ry * ry + rz * rz);
    float dist = rn + 1e-6f;
    float na = fmaxf(rn, 1e-6f);
    float nb = fmaxf(sqrtf(vx * vx + vy * vy + vz * vz), 1e-6f);
    float dir_score = (rx * vx + ry * vy + rz * vz) / (na * nb);

    float a0 = 1.0f / dist;
    float a1 = dir_score;
    float a2 = dn;

    // Layer 1: 3 -> 32 (scalar, tiny)
    float h[32];
#pragma unroll
    for (int j = 0; j < 32; j++) {
        float s = fmaf(a2, sW1[j * 3 + 2],
                 fmaf(a1, sW1[j * 3 + 1],
                 fmaf(a0, sW1[j * 3 + 0], sb1[j])));
        h[j] = fmaxf(s, 0.0f);
    }

    // Layer 2: 32 -> 32 with packed f32x2 FMA.
    // acc[jp] holds outputs (2jp, 2jp+1). 512 FFMA2 + 256 LDS.128 total.
    unsigned long long acc[16];
    const unsigned long long* b2p = reinterpret_cast<const unsigned long long*>(sb2);
#pragma unroll
    for (int jp = 0; jp < 16; jp++) acc[jp] = b2p[jp];

    const ulonglong2* w2q = reinterpret_cast<const ulonglong2*>(sW2t);
#pragma unroll
    for (int k = 0; k < 32; k++) {
        unsigned long long hk2 = pack2(h[k], h[k]);
#pragma unroll
        for (int q = 0; q < 8; q++) {          // rows j = 4q..4q+3 of column k
            ulonglong2 w = w2q[k * 8 + q];
            acc[2 * q]     = ffma2(hk2, w.x, acc[2 * q]);
            acc[2 * q + 1] = ffma2(hk2, w.y, acc[2 * q + 1]);
        }
    }

    // ReLU + Layer 3: 32 -> 1, sigmoid
    float s = sb3;
#pragma unroll
    for (int jp = 0; jp < 16; jp++) {
        float lo, hi;
        unpack2(acc[jp], lo, hi);
        s = fmaf(fmaxf(lo, 0.0f), sW3[2 * jp], s);
        s = fmaf(fmaxf(hi, 0.0f), sW3[2 * jp + 1], s);
    }
    float sig = 1.0f / (1.0f + __expf(-s));
    g_score_h[i] = __float2half(sig);
}

// ---------------------------------------------------------------------------
// Kernel 3: persistent gather. Each block copies the full fp16 score table
// into SMEM (200KB), then streams edges: int4 index load -> 4x LDS.U16 ->
// float4 store.
// ---------------------------------------------------------------------------
#define G_THREADS 1024
__global__ void gather_kernel(const int* __restrict__ tgt,
                              float* __restrict__ out,
                              int n_edges, int n_nodes) {
    extern __shared__ __align__(16) __half stab[];

    int n8 = (n_nodes + 7) >> 3;
    const uint4* src = reinterpret_cast<const uint4*>(g_score_h);
    uint4* dst = reinterpret_cast<uint4*>(stab);
    for (int k = threadIdx.x; k < n8; k += G_THREADS) dst[k] = src[k];
    __syncthreads();

    int n4 = n_edges >> 2;
    int stride = gridDim.x * G_THREADS;
    const int4* tv = reinterpret_cast<const int4*>(tgt);
    float4* ov = reinterpret_cast<float4*>(out);

    for (int j = blockIdx.x * G_THREADS + threadIdx.x; j < n4; j += stride) {
        int4 a = tv[j];
        float4 o;
        o.x = __half2float(stab[a.x]);
        o.y = __half2float(stab[a.y]);
        o.z = __half2float(stab[a.z]);
        o.w = __half2float(stab[a.w]);
        ov[j] = o;
    }

    if (blockIdx.x == 0 && threadIdx.x == 0) {
        for (int e = n4 << 2; e < n_edges; e++)
            out[e] = __half2float(stab[tgt[e]]);
    }
}

extern "C" void kernel_launch(void* const* d_in, const int* in_sizes, int n_in,
                              void* d_out, int out_size) {
    const float* x_t    = (const float*)d_in[0];
    const float* x_t_dt = (const float*)d_in[1];
    const int*   edge_index = (const int*)d_in[2];   // int32 (JAX x64 off)
    const float* W1 = (const float*)d_in[3];
    const float* b1 = (const float*)d_in[4];
    const float* W2 = (const float*)d_in[5];
    const float* b2 = (const float*)d_in[6];
    const float* W3 = (const float*)d_in[7];
    const float* b3 = (const float*)d_in[8];
    float* out = (float*)d_out;

    int n_nodes = in_sizes[0] / 7;
    int n_edges = in_sizes[2] / 2;
    const int* tgt = edge_index + n_edges;  // row 1 of (2, E)

    // Kernel 1: float4 master scan.
    int total = n_nodes * 7;
    int nv4 = total >> 2;
    find_master_kernel<<<(nv4 + 255) / 256, 256>>>(
        (const float4*)x_t, nv4, total, x_t);

    // Kernel 2: node scores.
    int nb_nodes = (n_nodes + NS_THREADS - 1) / NS_THREADS;
    node_score_kernel<<<nb_nodes, NS_THREADS>>>(x_t, x_t_dt, W1, b1, W2, b2, W3, b3, n_nodes);

    // Kernel 3: persistent gather with SMEM-resident fp16 table.
    size_t smem = ((size_t)(n_nodes + 7) & ~7ull) * sizeof(__half);
    cudaFuncSetAttribute(gather_kernel,
                         cudaFuncAttributeMaxDynamicSharedMemorySize,
                         (int)smem + 16);
    gather_kernel<<<148, G_THREADS, smem>>>(tgt, out, n_edges, n_nodes);
}